// round 7
// baseline (speedup 1.0000x reference)
#include <cuda_runtime.h>
#include <cuda_bf16.h>

#define RIR_LEN   8000
#define NIMG      1561
#define NSPLIT    4
#define NTH       256
#define NWARP     (NTH / 32)
#define PI_F      3.14159265358979323846f
#define INV_PI_F  0.3183098861837907f
#define FS_OVER_C 46.64723032069971f   /* 16000 / 343 */
#define MAXB      256

// Partial RIRs: layout part[sub][b][t] (sub-major) so combine reads coalesce.
__device__ float g_part[NSPLIT * MAXB * RIR_LEN];

__global__ void __launch_bounds__(NTH, 7)
rir_partial_kernel(const float* __restrict__ in, float* __restrict__ out, int B)
{
    __shared__ float srir[RIR_LEN];     // 32000 B  (total smem ~32.2KB -> 7 CTAs/SM)
    __shared__ float prm[10];
    __shared__ float roomS[3], micS[3], srcS[3];
    __shared__ float trp[11];           // tr^k
    __shared__ int   pfx[22];           // image-index prefix per gx shell

    const int b    = blockIdx.x >> 2;   // room
    const int sub  = blockIdx.x & 3;    // image-range split
    const int tid  = threadIdx.x;
    const int lane = tid & 31;
    const int warp = tid >> 5;

    if (tid < 10) prm[tid] = in[b * 10 + tid];
    if (tid < 22) {
        int n = tid, v;
        if (n <= 10) v = (n - 1) * n * (2 * n - 1) / 3 + (n - 1) * n + n;
        else { int m = 21 - n; v = NIMG - ((m - 1) * m * (2 * m - 1) / 3 + (m - 1) * m + m); }
        pfx[tid] = v;
    }
    {
        float4* s4 = (float4*)srir;
        for (int i = tid; i < RIR_LEN / 4; i += NTH)
            s4[i] = make_float4(0.f, 0.f, 0.f, 0.f);
    }
    __syncthreads();

    if (tid < 3) {
        float r = prm[tid];
        roomS[tid] = r;
        micS[tid]  = prm[3 + tid] * r;
        srcS[tid]  = prm[6 + tid] * r;
    }
    if (tid < 11) trp[tid] = powf(sqrtf(1.0f - prm[9]), (float)tid);

    // Per-thread Hann window table (register-resident, replaces shared htab):
    // (cos,sin)(pi*(t-40)/40) for t = lane, lane+32, lane+64.
    const float tm0 = (float)(lane - 40);
    const float tm1 = (float)(lane - 8);
    const float tm2 = (float)(lane + 24);
    float c0, s0, c1, s1, c2, s2;
    sincosf(PI_F * (1.0f / 40.0f) * tm0, &s0, &c0);
    sincosf(PI_F * (1.0f / 40.0f) * tm1, &s1, &c1);
    sincosf(PI_F * (1.0f / 40.0f) * tm2, &s2, &c2);
    const float sgn = (lane & 1) ? -1.0f : 1.0f;   // (-1)^t, t = lane+32r
    __syncthreads();

    const int is = (NIMG * sub)       / NSPLIT;
    const int ie = (NIMG * (sub + 1)) / NSPLIT;

    for (int i0 = is + warp * 32; i0 < ie; i0 += NWARP * 32) {
        const int i = i0 + lane;

        // ---------- lane-parallel per-image scalar phase ----------
        float frL = 0.0f, a2L = 0.0f, hcL = 0.0f, hsL = 0.0f;
        int   baseL = RIR_LEN;
        if (i < ie) {
            // decode image index -> (gx, gy, gz), |gx|+|gy|+|gz| <= 10
            int lo = 0, hi = 21;
#pragma unroll
            for (int it = 0; it < 5; it++) {
                int mid = (lo + hi) >> 1;
                if (i >= pfx[mid]) lo = mid; else hi = mid;
            }
            const int gx = lo - 10;
            const int ax = gx < 0 ? -gx : gx;
            const int R  = 10 - ax;
            const int j  = i - pfx[lo];
            const int M  = 2 * R * R + 2 * R + 1;
            const int rp1 = R + 1;
            int k;
            if (j < rp1 * rp1) k = (int)sqrtf((float)j + 0.5f);
            else               k = 2 * R - (int)sqrtf((float)(M - 1 - j) + 0.5f);
            const int Pk = (k <= R) ? k * k : M - (2 * R + 1 - k) * (2 * R + 1 - k);
            const int gy = k - R;
            const int ay = gy < 0 ? -gy : gy;
            const int gz = (j - Pk) - (R - ay);
            const int az = gz < 0 ? -gz : gz;

            const float att = trp[ax + ay + az];
            const int g3[3] = {gx, gy, gz};
            float d2 = 0.0f;
#pragma unroll
            for (int d = 0; d < 3; d++) {
                const int   g  = g3[d];
                const float gf = (float)g;
                const float ip = (g & 1) ? roomS[d] * (gf + 1.0f) - srcS[d]
                                         : roomS[d] * gf + srcS[d];
                const float df = ip - micS[d];
                d2 += df * df;
            }
            const float dist    = sqrtf(d2);
            const float amp     = __fdividef(att, dist);
            const float delay   = dist * FS_OVER_C;
            const float delay_i = ceilf(delay);
            // clamp frac away from 0: sin(pi*fr)/ (pi*x) then reproduces
            // sinc exactly enough (abs err ~1e-9*amp), killing the x==0 branch
            const float fr = fmaxf(delay_i - delay, 1e-9f);

            const float s = sinf(PI_F * fr);       // sin(pi*x) = s * (-1)^t
            float sA, cA;
            __sincosf(PI_F * (1.0f / 40.0f) * fr, &sA, &cA);

            frL   = fr;
            a2L   = amp * s * INV_PI_F;
            hcL   = 0.5f * cA;
            hsL   = 0.5f * sA;
            baseL = (int)delay_i - 40;
        }

        // ---------- warp-cooperative tap scatter (conflict-free) ----------
        const int nv = min(32, ie - i0);
        for (int jj = 0; jj < nv; jj++) {
            const int base = __shfl_sync(0xffffffffu, baseL, jj);
            if (base >= RIR_LEN) continue;         // fully clipped image
            const float fr = __shfl_sync(0xffffffffu, frL, jj);
            const float a2 = __shfl_sync(0xffffffffu, a2L, jj);
            const float hc = __shfl_sync(0xffffffffu, hcL, jj);
            const float hs = __shfl_sync(0xffffffffu, hsL, jj);
            const float a2s = a2 * sgn;

            {   // round 0: t = lane  (x in [-40,-8))
                const float x    = fr + tm0;
                const float hann = fmaf(hc, c0, fmaf(-hs, s0, 0.5f));
                const int   idx  = base + lane;
                if ((unsigned)idx < RIR_LEN)
                    atomicAdd(&srir[idx], __fdividef(a2s, x) * hann);
            }
            {   // round 1: t = lane+32
                const float x    = fr + tm1;
                const float hann = fmaf(hc, c1, fmaf(-hs, s1, 0.5f));
                const int   idx  = base + lane + 32;
                if ((unsigned)idx < RIR_LEN)
                    atomicAdd(&srir[idx], __fdividef(a2s, x) * hann);
            }
            {   // round 2: t = lane+64, t<=79 (t=80 tap is identically zero)
                const float x    = fr + tm2;
                const float hann = fmaf(hc, c2, fmaf(-hs, s2, 0.5f));
                const int   idx  = base + lane + 64;
                if (lane < 16 && (unsigned)idx < RIR_LEN)
                    atomicAdd(&srir[idx], __fdividef(a2s, x) * hann);
            }
        }
    }
    __syncthreads();

    // write this CTA's partial RIR (coalesced, vectorized)
    {
        float4*       p4 = (float4*)(g_part + ((size_t)sub * MAXB + b) * RIR_LEN);
        const float4* s4 = (const float4*)srir;
        for (int i = tid; i < RIR_LEN / 4; i += NTH) p4[i] = s4[i];
    }

    // TOA (once per room)
    if (sub == 0 && tid == 0) {
        const float d0 = micS[0] - srcS[0];
        const float d1 = micS[1] - srcS[1];
        const float d2 = micS[2] - srcS[2];
        out[(size_t)B * RIR_LEN + b] =
            40.0f + FS_OVER_C * sqrtf(d0 * d0 + d1 * d1 + d2 * d2);
    }
}

__global__ void __launch_bounds__(NTH)
rir_combine_kernel(float* __restrict__ out, int n4)
{
    const int g = blockIdx.x * NTH + threadIdx.x;
    if (g < n4) {
        const float4* p  = (const float4*)g_part;
        const int     S4 = MAXB * RIR_LEN / 4;
        float4 a = p[g];
        float4 bb = p[g + S4];
        float4 c = p[g + 2 * S4];
        float4 d = p[g + 3 * S4];
        float4 r;
        r.x = (a.x + bb.x) + (c.x + d.x);
        r.y = (a.y + bb.y) + (c.y + d.y);
        r.z = (a.z + bb.z) + (c.z + d.z);
        r.w = (a.w + bb.w) + (c.w + d.w);
        ((float4*)out)[g] = r;
    }
}

extern "C" void kernel_launch(void* const* d_in, const int* in_sizes, int n_in,
                              void* d_out, int out_size)
{
    const float* in  = (const float*)d_in[0];
    float*       out = (float*)d_out;
    const int B  = in_sizes[0] / 10;         // 256 rooms x 10 params
    const int n4 = B * RIR_LEN / 4;
    // hint max smem carveout so 7 CTAs/SM fit (idempotent, capture-safe)
    cudaFuncSetAttribute(rir_partial_kernel,
                         cudaFuncAttributePreferredSharedMemoryCarveout, 100);
    rir_partial_kernel<<<B * NSPLIT, NTH>>>(in, out, B);
    rir_combine_kernel<<<(n4 + NTH - 1) / NTH, NTH>>>(out, n4);
}

// round 9
// speedup vs baseline: 1.2989x; 1.2989x over previous
#include <cuda_runtime.h>
#include <cuda_bf16.h>

#define RIR_LEN   8000
#define NIMG      1561
#define NSPLIT    4
#define NTH       256
#define NWARP     (NTH / 32)
#define PI_F      3.14159265358979323846f
#define INV_PI_F  0.3183098861837907f
#define FS_OVER_C 46.64723032069971f   /* 16000 / 343 */

// ---------------------------------------------------------------------------
// Kernel 0: zero the RIR output region + compute TOA per room.
// ---------------------------------------------------------------------------
__global__ void __launch_bounds__(NTH)
rir_init_kernel(const float* __restrict__ in, float* __restrict__ out,
                int B, int n4)
{
    const int g = blockIdx.x * NTH + threadIdx.x;
    if (g < n4)
        ((float4*)out)[g] = make_float4(0.f, 0.f, 0.f, 0.f);
    if (g < B) {
        const float rx = in[g * 10 + 0], ry = in[g * 10 + 1], rz = in[g * 10 + 2];
        const float d0 = (in[g * 10 + 3] - in[g * 10 + 6]) * rx;
        const float d1 = (in[g * 10 + 4] - in[g * 10 + 7]) * ry;
        const float d2 = (in[g * 10 + 5] - in[g * 10 + 8]) * rz;
        out[(size_t)B * RIR_LEN + g] =
            40.0f + FS_OVER_C * sqrtf(d0 * d0 + d1 * d1 + d2 * d2);
    }
}

// ---------------------------------------------------------------------------
// Kernel 1: per-(room, image-range) partial RIR in shared memory, then
// RED.ADD directly into out (no combine pass, no scratch).
// ---------------------------------------------------------------------------
__global__ void __launch_bounds__(NTH, 6)
rir_partial_kernel(const float* __restrict__ in, float* __restrict__ out, int B)
{
    __shared__ float  srir[RIR_LEN];     // 32000 B
    __shared__ float2 htab[81];          // (cos,sin)(pi*(t-40)/40)
    __shared__ float  prm[10];
    __shared__ float  roomS[3], micS[3], srcS[3];
    __shared__ float  trp[11];           // tr^k
    __shared__ int    pfx[22];           // image-index prefix per gx shell

    const int b    = blockIdx.x >> 2;    // room
    const int sub  = blockIdx.x & 3;     // image-range split
    const int tid  = threadIdx.x;
    const int lane = tid & 31;
    const int warp = tid >> 5;

    if (tid < 10) prm[tid] = in[b * 10 + tid];
    if (tid < 22) {
        int n = tid, v;
        if (n <= 10) v = (n - 1) * n * (2 * n - 1) / 3 + (n - 1) * n + n;
        else { int m = 21 - n; v = NIMG - ((m - 1) * m * (2 * m - 1) / 3 + (m - 1) * m + m); }
        pfx[tid] = v;
    }
    if (tid < 81) {
        float sc, cc;
        sincosf(PI_F * (1.0f / 40.0f) * (float)(tid - 40), &sc, &cc);
        htab[tid] = make_float2(cc, sc);
    }
    {
        float4* s4 = (float4*)srir;
        for (int i = tid; i < RIR_LEN / 4; i += NTH)
            s4[i] = make_float4(0.f, 0.f, 0.f, 0.f);
    }
    __syncthreads();

    if (tid < 3) {
        float r = prm[tid];
        roomS[tid] = r;
        micS[tid]  = prm[3 + tid] * r;
        srcS[tid]  = prm[6 + tid] * r;
    }
    if (tid < 11) trp[tid] = powf(sqrtf(1.0f - prm[9]), (float)tid);
    const float sgn = (lane & 1) ? -1.0f : 1.0f;   // (-1)^t, t = lane+32r
    __syncthreads();

    const int is = (NIMG * sub)       / NSPLIT;
    const int ie = (NIMG * (sub + 1)) / NSPLIT;

    for (int i0 = is + warp * 32; i0 < ie; i0 += NWARP * 32) {
        const int i = i0 + lane;

        // ---------- lane-parallel per-image scalar phase ----------
        float frL = 0.0f, a2L = 0.0f, hcL = 0.0f, hsL = 0.0f;
        int   baseL = RIR_LEN;
        if (i < ie) {
            // decode image index -> (gx, gy, gz), |gx|+|gy|+|gz| <= 10
            int lo = 0, hi = 21;
#pragma unroll
            for (int it = 0; it < 5; it++) {
                int mid = (lo + hi) >> 1;
                if (i >= pfx[mid]) lo = mid; else hi = mid;
            }
            const int gx = lo - 10;
            const int ax = gx < 0 ? -gx : gx;
            const int R  = 10 - ax;
            const int j  = i - pfx[lo];
            const int M  = 2 * R * R + 2 * R + 1;
            const int rp1 = R + 1;
            int k;
            if (j < rp1 * rp1) k = (int)sqrtf((float)j + 0.5f);
            else               k = 2 * R - (int)sqrtf((float)(M - 1 - j) + 0.5f);
            const int Pk = (k <= R) ? k * k : M - (2 * R + 1 - k) * (2 * R + 1 - k);
            const int gy = k - R;
            const int ay = gy < 0 ? -gy : gy;
            const int gz = (j - Pk) - (R - ay);
            const int az = gz < 0 ? -gz : gz;

            const float att = trp[ax + ay + az];
            const int g3[3] = {gx, gy, gz};
            float d2 = 0.0f;
#pragma unroll
            for (int d = 0; d < 3; d++) {
                const int   g  = g3[d];
                const float gf = (float)g;
                const float ip = (g & 1) ? roomS[d] * (gf + 1.0f) - srcS[d]
                                         : roomS[d] * gf + srcS[d];
                const float df = ip - micS[d];
                d2 += df * df;
            }
            const float dist    = sqrtf(d2);
            const float amp     = __fdividef(att, dist);
            const float delay   = dist * FS_OVER_C;
            const float delay_i = ceilf(delay);
            // clamp frac away from 0: sin(pi*fr)/(pi*x) then reproduces
            // sinc(0)=1 to ~1e-9 abs, killing the x==0 special case
            const float fr = fmaxf(delay_i - delay, 1e-9f);

            const float s = sinf(PI_F * fr);       // sin(pi*x) = s*(-1)^t
            float sA, cA;
            __sincosf(PI_F * (1.0f / 40.0f) * fr, &sA, &cA);

            frL   = fr;
            a2L   = amp * s * INV_PI_F;
            hcL   = 0.5f * cA;
            hsL   = 0.5f * sA;
            baseL = (int)delay_i - 40;
        }

        // ---------- warp-cooperative tap scatter (conflict-free) ----------
        const int nv = min(32, ie - i0);
        for (int jj = 0; jj < nv; jj++) {
            const int base = __shfl_sync(0xffffffffu, baseL, jj);
            if (base >= RIR_LEN) continue;         // fully clipped image
            const float fr = __shfl_sync(0xffffffffu, frL, jj);
            const float a2 = __shfl_sync(0xffffffffu, a2L, jj);
            const float hc = __shfl_sync(0xffffffffu, hcL, jj);
            const float hs = __shfl_sync(0xffffffffu, hsL, jj);
            const float a2s = a2 * sgn;

            {   // round 0: t = lane
                const float2 cs  = htab[lane];
                const float x    = fr + (float)(lane - 40);
                const float hann = fmaf(hc, cs.x, fmaf(-hs, cs.y, 0.5f));
                const int   idx  = base + lane;
                if ((unsigned)idx < RIR_LEN)
                    atomicAdd(&srir[idx], __fdividef(a2s, x) * hann);
            }
            {   // round 1: t = lane+32
                const float2 cs  = htab[lane + 32];
                const float x    = fr + (float)(lane - 8);
                const float hann = fmaf(hc, cs.x, fmaf(-hs, cs.y, 0.5f));
                const int   idx  = base + lane + 32;
                if ((unsigned)idx < RIR_LEN)
                    atomicAdd(&srir[idx], __fdividef(a2s, x) * hann);
            }
            if (lane < 16) {   // round 2: t = lane+64 (t=80 tap is zero)
                const float2 cs  = htab[lane + 64];
                const float x    = fr + (float)(lane + 24);
                const float hann = fmaf(hc, cs.x, fmaf(-hs, cs.y, 0.5f));
                const int   idx  = base + lane + 64;
                if ((unsigned)idx < RIR_LEN)
                    atomicAdd(&srir[idx], __fdividef(a2s, x) * hann);
            }
        }
    }
    __syncthreads();

    // RED.ADD this CTA's partial RIR into the output row (coalesced, no-return)
    {
        float* orow = out + (size_t)b * RIR_LEN;
        for (int i = tid; i < RIR_LEN; i += NTH)
            atomicAdd(&orow[i], srir[i]);
    }
}

extern "C" void kernel_launch(void* const* d_in, const int* in_sizes, int n_in,
                              void* d_out, int out_size)
{
    const float* in  = (const float*)d_in[0];
    float*       out = (float*)d_out;
    const int B  = in_sizes[0] / 10;         // 256 rooms x 10 params
    const int n4 = B * RIR_LEN / 4;
    rir_init_kernel<<<(n4 + NTH - 1) / NTH, NTH>>>(in, out, B, n4);
    rir_partial_kernel<<<B * NSPLIT, NTH>>>(in, out, B);
}

// round 11
// speedup vs baseline: 1.6021x; 1.2335x over previous
#include <cuda_runtime.h>
#include <cuda_bf16.h>

#define RIR_LEN   8000
#define NIMG      1561
#define NSPLIT    7
#define NTH       512
#define NWARP     (NTH / 32)
#define PI_F      3.14159265358979323846f
#define INV_PI_F  0.3183098861837907f
#define FS_OVER_C 46.64723032069971f   /* 16000 / 343 */

// ---------------------------------------------------------------------------
// Per-(room, image-range) partial RIR in shared memory, RED.ADD into out.
// out RIR region must be pre-zeroed (memset node in kernel_launch).
// ---------------------------------------------------------------------------
__global__ void __launch_bounds__(NTH, 4)
rir_partial_kernel(const float* __restrict__ in, float* __restrict__ out, int B)
{
    __shared__ float  srir[RIR_LEN];     // 32000 B
    __shared__ float2 htab[81];          // (cos,sin)(pi*(t-40)/40)
    __shared__ float  prm[10];
    __shared__ float  roomS[3], micS[3], srcS[3];
    __shared__ float  trp[11];           // tr^k
    __shared__ int    pfx[22];           // image-index prefix per gx shell

    const int b    = blockIdx.x / NSPLIT;   // room
    const int sub  = blockIdx.x % NSPLIT;   // image-range split
    const int tid  = threadIdx.x;
    const int lane = tid & 31;
    const int warp = tid >> 5;

    if (tid < 10) prm[tid] = in[b * 10 + tid];
    if (tid < 22) {
        int n = tid, v;
        if (n <= 10) v = (n - 1) * n * (2 * n - 1) / 3 + (n - 1) * n + n;
        else { int m = 21 - n; v = NIMG - ((m - 1) * m * (2 * m - 1) / 3 + (m - 1) * m + m); }
        pfx[tid] = v;
    }
    if (tid < 81) {
        float sc, cc;
        sincosf(PI_F * (1.0f / 40.0f) * (float)(tid - 40), &sc, &cc);
        htab[tid] = make_float2(cc, sc);
    }
    {
        float4* s4 = (float4*)srir;
        for (int i = tid; i < RIR_LEN / 4; i += NTH)
            s4[i] = make_float4(0.f, 0.f, 0.f, 0.f);
    }
    __syncthreads();

    if (tid < 3) {
        float r = prm[tid];
        roomS[tid] = r;
        micS[tid]  = prm[3 + tid] * r;
        srcS[tid]  = prm[6 + tid] * r;
    }
    if (tid < 11) trp[tid] = powf(sqrtf(1.0f - prm[9]), (float)tid);
    const float sgn = (lane & 1) ? -1.0f : 1.0f;   // (-1)^t, t = lane+32r
    __syncthreads();

    // image sub-range for this CTA, chunked evenly over warps
    const int is    = (NIMG * sub)       / NSPLIT;
    const int ie    = (NIMG * (sub + 1)) / NSPLIT;
    const int chunk = (ie - is + NWARP - 1) / NWARP;
    const int ws    = min(is + warp * chunk, ie);
    const int we    = min(ws + chunk, ie);

    for (int i0 = ws; i0 < we; i0 += 32) {
        const int i = i0 + lane;

        // ---------- lane-parallel per-image scalar phase ----------
        float frL = 0.0f, a2L = 0.0f, hcL = 0.0f, hsL = 0.0f;
        int   baseL = RIR_LEN;
        if (i < we) {
            // decode image index -> (gx, gy, gz), |gx|+|gy|+|gz| <= 10
            int lo = 0, hi = 21;
#pragma unroll
            for (int it = 0; it < 5; it++) {
                int mid = (lo + hi) >> 1;
                if (i >= pfx[mid]) lo = mid; else hi = mid;
            }
            const int gx = lo - 10;
            const int ax = gx < 0 ? -gx : gx;
            const int R  = 10 - ax;
            const int j  = i - pfx[lo];
            const int M  = 2 * R * R + 2 * R + 1;
            const int rp1 = R + 1;
            int k;
            if (j < rp1 * rp1) k = (int)sqrtf((float)j + 0.5f);
            else               k = 2 * R - (int)sqrtf((float)(M - 1 - j) + 0.5f);
            const int Pk = (k <= R) ? k * k : M - (2 * R + 1 - k) * (2 * R + 1 - k);
            const int gy = k - R;
            const int ay = gy < 0 ? -gy : gy;
            const int gz = (j - Pk) - (R - ay);
            const int az = gz < 0 ? -gz : gz;

            const float att = trp[ax + ay + az];
            const int g3[3] = {gx, gy, gz};
            float d2 = 0.0f;
#pragma unroll
            for (int d = 0; d < 3; d++) {
                const int   g  = g3[d];
                const float gf = (float)g;
                const float ip = (g & 1) ? roomS[d] * (gf + 1.0f) - srcS[d]
                                         : roomS[d] * gf + srcS[d];
                const float df = ip - micS[d];
                d2 += df * df;
            }
            const float dist    = sqrtf(d2);
            const float amp     = __fdividef(att, dist);
            const float delay   = dist * FS_OVER_C;
            const float delay_i = ceilf(delay);
            // clamp frac away from 0: sin(pi*fr)/(pi*x) reproduces sinc(0)=1
            // to ~1e-9 abs, so no x==0 special case needed
            const float fr = fmaxf(delay_i - delay, 1e-9f);

            // NOTE: must be the ACCURATE sinf. __sinf has ~3.6e-7 ABSOLUTE
            // error; divided by pi*fr (fr ~ 1e-9 for near-integer delays) it
            // corrupts the dominant tap by orders of magnitude (R10 failure).
            const float s = sinf(PI_F * fr);       // sin(pi*x) = s*(-1)^t
            float sA, cA;
            __sincosf(PI_F * (1.0f / 40.0f) * fr, &sA, &cA);

            frL   = fr;
            a2L   = amp * s * INV_PI_F;
            hcL   = 0.5f * cA;
            hsL   = 0.5f * sA;
            baseL = (int)delay_i - 40;
        }

        // ---------- warp-cooperative tap scatter (conflict-free) ----------
        const int nv = min(32, we - i0);
        for (int jj = 0; jj < nv; jj++) {
            const int base = __shfl_sync(0xffffffffu, baseL, jj);
            if (base >= RIR_LEN) continue;         // fully clipped image
            const float fr = __shfl_sync(0xffffffffu, frL, jj);
            const float a2 = __shfl_sync(0xffffffffu, a2L, jj);
            const float hc = __shfl_sync(0xffffffffu, hcL, jj);
            const float hs = __shfl_sync(0xffffffffu, hsL, jj);
            const float a2s = a2 * sgn;

            const float2 cs0 = htab[lane];
            const float2 cs1 = htab[lane + 32];
            const float x0 = fr + (float)(lane - 40);
            const float x1 = fr + (float)(lane - 8);
            const float h0 = fmaf(hc, cs0.x, fmaf(-hs, cs0.y, 0.5f));
            const float h1 = fmaf(hc, cs1.x, fmaf(-hs, cs1.y, 0.5f));

            if (base >= 0 && base < RIR_LEN - 80) {
                // interior fast path: no per-tap bounds checks
                atomicAdd(&srir[base + lane],      __fdividef(a2s, x0) * h0);
                atomicAdd(&srir[base + lane + 32], __fdividef(a2s, x1) * h1);
                if (lane < 16) {
                    const float2 cs2 = htab[lane + 64];
                    const float x2 = fr + (float)(lane + 24);
                    const float h2 = fmaf(hc, cs2.x, fmaf(-hs, cs2.y, 0.5f));
                    atomicAdd(&srir[base + lane + 64], __fdividef(a2s, x2) * h2);
                }
            } else {
                const int i0x = base + lane;
                if ((unsigned)i0x < RIR_LEN)
                    atomicAdd(&srir[i0x], __fdividef(a2s, x0) * h0);
                const int i1x = base + lane + 32;
                if ((unsigned)i1x < RIR_LEN)
                    atomicAdd(&srir[i1x], __fdividef(a2s, x1) * h1);
                if (lane < 16) {
                    const float2 cs2 = htab[lane + 64];
                    const float x2 = fr + (float)(lane + 24);
                    const float h2 = fmaf(hc, cs2.x, fmaf(-hs, cs2.y, 0.5f));
                    const int i2x = base + lane + 64;
                    if ((unsigned)i2x < RIR_LEN)
                        atomicAdd(&srir[i2x], __fdividef(a2s, x2) * h2);
                }
            }
        }
    }
    __syncthreads();

    // RED.ADD this CTA's partial RIR into the output row (coalesced, no-return)
    {
        float* orow = out + (size_t)b * RIR_LEN;
        for (int i = tid; i < RIR_LEN; i += NTH)
            atomicAdd(&orow[i], srir[i]);
    }

    // TOA (single writer per room, plain store)
    if (sub == 0 && tid == 0) {
        const float d0 = micS[0] - srcS[0];
        const float d1 = micS[1] - srcS[1];
        const float d2 = micS[2] - srcS[2];
        out[(size_t)B * RIR_LEN + b] =
            40.0f + FS_OVER_C * sqrtf(d0 * d0 + d1 * d1 + d2 * d2);
    }
}

extern "C" void kernel_launch(void* const* d_in, const int* in_sizes, int n_in,
                              void* d_out, int out_size)
{
    const float* in  = (const float*)d_in[0];
    float*       out = (float*)d_out;
    const int B = in_sizes[0] / 10;          // 256 rooms x 10 params
    // zero RIR region via capturable memset node (TOA region overwritten later)
    cudaMemsetAsync(out, 0, (size_t)B * RIR_LEN * sizeof(float));
    rir_partial_kernel<<<B * NSPLIT, NTH>>>(in, out, B);
}